// round 7
// baseline (speedup 1.0000x reference)
#include <cuda_runtime.h>
#include <cstdint>
#include <math.h>

#define NB 8
#define NT 512
#define NWARP 16   // warps per CTA; 8*16 = 128 global warps, 2 elements each

// ---------------- dynamic smem layout ------------------------------------------
struct __align__(16) SmemLayout {
    float whh[96 * 256];   // this CTA's 96 w_hh rows
    float wih[96 * 256];   // this CTA's 96 w_ih rows
    float enc[20 * 256];
    float h0[256];
    float comb[256];
    float hnew[256];
    float l[32];
};

// ---------------- helpers ------------------------------------------------------
__device__ __forceinline__ float warp_sum(float v) {
#pragma unroll
    for (int o = 16; o; o >>= 1) v += __shfl_xor_sync(0xffffffffu, v, o);
    return v;
}
__device__ __forceinline__ float warp_max(float v) {
#pragma unroll
    for (int o = 16; o; o >>= 1) v = fmaxf(v, __shfl_xor_sync(0xffffffffu, v, o));
    return v;
}
__device__ __forceinline__ float dot4(float4 a, float4 b) {
    return a.x * b.x + a.y * b.y + a.z * b.z + a.w * b.w;
}
__device__ __forceinline__ uint32_t smem_u32(const void* p) {
    uint32_t a;
    asm("{.reg .u64 t; cvta.to.shared.u64 t,%1; cvt.u32.u64 %0,t;}" : "=r"(a) : "l"(p));
    return a;
}
__device__ __forceinline__ void cp16(void* dst, const void* src) {
    uint32_t d = smem_u32(dst);
    asm volatile("cp.async.cg.shared.global [%0],[%1],16;" :: "r"(d), "l"(src) : "memory");
}
__device__ __forceinline__ void cp_commit() {
    asm volatile("cp.async.commit_group;" ::: "memory");
}
// store 4B to the same smem offset in CTA `rank` of the cluster
__device__ __forceinline__ void st_cluster(uint32_t laddr, int rank, float v) {
    uint32_t ra;
    asm("mapa.shared::cluster.u32 %0,%1,%2;" : "=r"(ra) : "r"(laddr), "r"(rank));
    asm volatile("st.shared::cluster.f32 [%0],%1;" :: "r"(ra), "f"(v) : "memory");
}
// HW cluster barrier (release/acquire at cluster scope covers DSMEM stores)
__device__ __forceinline__ void csync() {
    asm volatile("barrier.cluster.arrive.aligned;" ::: "memory");
    asm volatile("barrier.cluster.wait.aligned;" ::: "memory");
}

// ---------------- fused decoder step -------------------------------------------
__global__ void __launch_bounds__(NT, 1) __cluster_dims__(NB, 1, 1)
attn_decoder_fused(const int* __restrict__ inp,
                   const float* __restrict__ hidden,   // [256]
                   const float* __restrict__ enc,      // [20,256]
                   const int* __restrict__ cond,       // [2]
                   const int* __restrict__ is_head,    // [1]
                   const float* __restrict__ emb,      // [29,256]
                   const float* __restrict__ w_l2d,    // [256,264]
                   const float* __restrict__ b_l2d,
                   const float* __restrict__ w_attn,   // [20,512]
                   const float* __restrict__ b_attn,
                   const float* __restrict__ w_comb,   // [256,512]
                   const float* __restrict__ b_comb,
                   const float* __restrict__ w_ih,     // [768,256]
                   const float* __restrict__ w_hh,     // [768,256]
                   const float* __restrict__ b_ih,
                   const float* __restrict__ b_hh,
                   const float* __restrict__ w_out,    // [29,256]
                   const float* __restrict__ b_out,
                   float* __restrict__ out)            // [305]
{
    extern __shared__ SmemLayout sm[];

    const int tid  = threadIdx.x;
    const int lane = tid & 31;
    const int wrp  = tid >> 5;                        // 0..15
    const int bx   = blockIdx.x;
    const int gw   = bx * NWARP + wrp;                // 0..127
    const int e0i  = gw, e1i = gw + 128;              // elements owned by this warp

    // ---- t=0: async-stage enc + w_hh (group A) and w_ih (group B) -----------
    // local row layout: lr = g*32 + e*16 + w  ->  global row g*256 + e*128 + bx*16 + w
    for (int i = tid; i < 20 * 64; i += NT)
        cp16(&sm->enc[i * 4], enc + i * 4);
#pragma unroll
    for (int i = tid; i < 96 * 64; i += NT) {
        int lr  = i >> 6;
        int col = (i & 63) * 4;
        int g = lr >> 5, e = (lr >> 4) & 1, w = lr & 15;
        int grow = g * 256 + e * 128 + bx * 16 + w;
        cp16(&sm->whh[lr * 256 + col], w_hh + grow * 256 + col);
    }
    cp_commit();                                       // group A
#pragma unroll
    for (int i = tid; i < 96 * 64; i += NT) {
        int lr  = i >> 6;
        int col = (i & 63) * 4;
        int g = lr >> 5, e = (lr >> 4) & 1, w = lr & 15;
        int grow = g * 256 + e * 128 + bx * 16 + w;
        cp16(&sm->wih[lr * 256 + col], w_ih + grow * 256 + col);
    }
    cp_commit();                                       // group B

    const int head = __ldg(is_head);
    const float* erow = emb + __ldg(inp) * 256;

    // per-lane slices of hidden and embedded
    float4 hx0 = __ldg((const float4*)hidden + lane);
    float4 hx1 = __ldg((const float4*)hidden + 32 + lane);
    float4 e0  = __ldg((const float4*)erow + lane);
    float4 e1  = __ldg((const float4*)erow + 32 + lane);
    float  h_e0 = __ldg(hidden + e0i);                 // for GRU (!head path)
    float  h_e1 = __ldg(hidden + e1i);

    // ---- P1: h0 rows e0i,e1i (head path) + emb-half partials ----------------
    float h00 = 0.f, h01 = 0.f;
    if (head) {
        int c0 = __ldg(cond), c1 = __ldg(cond + 1);
#pragma unroll
        for (int e = 0; e < 2; e++) {
            const int o = e ? e1i : e0i;
            const float* wr = w_l2d + o * 264;
            float s = dot4(__ldg((const float4*)wr + lane), hx0) +
                      dot4(__ldg((const float4*)(wr + 128) + lane), hx1);
            if (lane < 8) {
                float xv = (lane == c0 || lane == 4 + c1) ? 1.f : 0.f;
                s += wr[256 + lane] * xv;
            }
            s = warp_sum(s) + __ldg(b_l2d + o);
            if (e) h01 = s; else h00 = s;
        }
        if (lane < 8)       st_cluster(smem_u32(&sm->h0[e0i]), lane, h00);
        else if (lane < 16) st_cluster(smem_u32(&sm->h0[e1i]), lane - 8, h01);
    }
    // comb emb-half partials (per-lane, finished in P2)
    const float* wc0 = w_comb + e0i * 512;
    const float* wc1 = w_comb + e1i * 512;
    float ce0 = dot4(__ldg((const float4*)wc0 + lane), e0) +
                dot4(__ldg((const float4*)wc0 + 32 + lane), e1);
    float ce1 = dot4(__ldg((const float4*)wc1 + lane), e0) +
                dot4(__ldg((const float4*)wc1 + 32 + lane), e1);
    // attn rows per-CTA redundant: r1=wrp, r2=16+wrp (wrp<4)
    float ae1, ae2 = 0.f;
    {
        const float* wa = w_attn + wrp * 512;
        ae1 = dot4(__ldg((const float4*)wa + lane), e0) +
              dot4(__ldg((const float4*)wa + 32 + lane), e1);
        if (wrp < 4) {
            const float* wb = w_attn + (16 + wrp) * 512;
            ae2 = dot4(__ldg((const float4*)wb + lane), e0) +
                  dot4(__ldg((const float4*)wb + 32 + lane), e1);
        }
    }
    // register-prefetch P2 small weights (overlaps cs1 wait)
    float4 wa1_0, wa1_1, wa2_0, wa2_1;
    {
        const float* wa = w_attn + wrp * 512 + 256;
        wa1_0 = __ldg((const float4*)wa + lane);
        wa1_1 = __ldg((const float4*)wa + 32 + lane);
        if (wrp < 4) {
            const float* wb = w_attn + (16 + wrp) * 512 + 256;
            wa2_0 = __ldg((const float4*)wb + lane);
            wa2_1 = __ldg((const float4*)wb + 32 + lane);
        }
    }
    float4 wch0_0 = __ldg((const float4*)(wc0 + 256) + lane);
    float4 wch0_1 = __ldg((const float4*)(wc0 + 256) + 32 + lane);
    float4 wch1_0 = __ldg((const float4*)(wc1 + 256) + lane);
    float4 wch1_1 = __ldg((const float4*)(wc1 + 256) + 32 + lane);
    csync();                                                       // ---- cs1
    asm volatile("cp.async.wait_group 1;" ::: "memory");           // enc + whh done
    __syncthreads();

    // ---- P2: gh from SMEM + attn logits + softmax + attn_applied + comb -----
    float4 x0, x1;
    if (head) { x0 = *((const float4*)sm->h0 + lane); x1 = *((const float4*)sm->h0 + 32 + lane); }
    else      { x0 = hx0; x1 = hx1; }
    float ghv[6];
#pragma unroll
    for (int r = 0; r < 6; r++) {
        const int g = r % 3, e = r / 3;
        const float* w = &sm->whh[((g * 2 + e) * 16 + wrp) * 256];
        const int o = g * 256 + (e ? e1i : e0i);
        ghv[r] = warp_sum(dot4(*((const float4*)w + lane), x0) +
                          dot4(*((const float4*)w + 32 + lane), x1)) + __ldg(b_hh + o);
    }
    {
        float s = warp_sum(ae1 + dot4(wa1_0, x0) + dot4(wa1_1, x1));
        if (lane == 0) sm->l[wrp] = s + __ldg(b_attn + wrp);
        if (wrp < 4) {
            float s2 = warp_sum(ae2 + dot4(wa2_0, x0) + dot4(wa2_1, x1));
            if (lane == 0) sm->l[16 + wrp] = s2 + __ldg(b_attn + 16 + wrp);
        }
    }
    __syncthreads();                                   // logits ready (CTA-local)
    {
        float v = (lane < 20) ? sm->l[lane] : -1e30f;
        float m = warp_max(v);
        float ex = (lane < 20) ? expf(v - m) : 0.f;
        float sum = warp_sum(ex);
        float w = ex / sum;
        if (gw == 0 && lane < 20) out[285 + lane] = w;
        float4 a0 = {0.f,0.f,0.f,0.f}, a1 = {0.f,0.f,0.f,0.f};
#pragma unroll
        for (int l = 0; l < 20; l++) {
            float wl = __shfl_sync(0xffffffffu, w, l);
            float4 q0 = *((const float4*)(sm->enc + l * 256) + lane);
            float4 q1 = *((const float4*)(sm->enc + l * 256) + 32 + lane);
            a0.x += wl*q0.x; a0.y += wl*q0.y; a0.z += wl*q0.z; a0.w += wl*q0.w;
            a1.x += wl*q1.x; a1.y += wl*q1.y; a1.z += wl*q1.z; a1.w += wl*q1.w;
        }
        float sc0 = warp_sum(ce0 + dot4(wch0_0, a0) + dot4(wch0_1, a1));
        float sc1 = warp_sum(ce1 + dot4(wch1_0, a0) + dot4(wch1_1, a1));
        sc0 = fmaxf(sc0 + __ldg(b_comb + e0i), 0.f);
        sc1 = fmaxf(sc1 + __ldg(b_comb + e1i), 0.f);
        if (lane < 8)       st_cluster(smem_u32(&sm->comb[e0i]), lane, sc0);
        else if (lane < 16) st_cluster(smem_u32(&sm->comb[e1i]), lane - 8, sc1);
    }
    asm volatile("cp.async.wait_group 0;" ::: "memory");           // wih done
    csync();                                                       // ---- cs2
    __syncthreads();

    // ---- P3: gi from SMEM + fused GRU (gh in registers) ---------------------
    {
        float4 c0 = *((const float4*)sm->comb + lane);
        float4 c1 = *((const float4*)sm->comb + 32 + lane);
        float gi[6];
#pragma unroll
        for (int r = 0; r < 6; r++) {
            const int g = r % 3, e = r / 3;
            const float* w = &sm->wih[((g * 2 + e) * 16 + wrp) * 256];
            const int o = g * 256 + (e ? e1i : e0i);
            gi[r] = warp_sum(dot4(*((const float4*)w + lane), c0) +
                             dot4(*((const float4*)w + 32 + lane), c1)) + __ldg(b_ih + o);
        }
#pragma unroll
        for (int e = 0; e < 2; e++) {
            const int o = e ? e1i : e0i;
            float h0o = head ? (e ? h01 : h00) : (e ? h_e1 : h_e0);
            float r = 1.f / (1.f + expf(-(gi[e] * 0.f + (e ? gi[3] : gi[0]) + ghv[e ? 3 : 0])));
            float z = 1.f / (1.f + expf(-((e ? gi[4] : gi[1]) + ghv[e ? 4 : 1])));
            float n = tanhf((e ? gi[5] : gi[2]) + r * ghv[e ? 5 : 2]);
            float h = (1.f - z) * n + z * h0o;
            if (lane == 0) {
                st_cluster(smem_u32(&sm->hnew[o]), 0, h);   // to CTA0 only
                out[29 + o] = h;
            }
        }
    }
    // register-prefetch P4 weights (CTA0)
    float4 wo[2][2]; float bo[2];
    if (bx == 0) {
#pragma unroll
        for (int r = 0; r < 2; r++) {
            const int o = wrp * 2 + r;
            if (o < 29) {
                const float* w = w_out + o * 256;
                wo[r][0] = __ldg((const float4*)w + lane);
                wo[r][1] = __ldg((const float4*)w + 32 + lane);
                bo[r] = __ldg(b_out + o);
            }
        }
    }
    csync();                                                       // ---- cs3
    if (bx != 0) return;

    // ---- P4 (CTA0): output logits + log_softmax -----------------------------
    {
        float4 h0x = *((const float4*)sm->hnew + lane);
        float4 h1x = *((const float4*)sm->hnew + 32 + lane);
#pragma unroll
        for (int r = 0; r < 2; r++) {
            const int o = wrp * 2 + r;
            if (o < 29) {
                float s = warp_sum(dot4(wo[r][0], h0x) + dot4(wo[r][1], h1x)) + bo[r];
                if (lane == 0) sm->l[o] = s;
            }
        }
    }
    __syncthreads();
    if (wrp == 0) {
        float v = (lane < 29) ? sm->l[lane] : -1e30f;
        float m = warp_max(v);
        float e = (lane < 29) ? expf(v - m) : 0.f;
        float sum = warp_sum(e);
        float ls = logf(sum);
        if (lane < 29) out[lane] = v - m - ls;
    }
}

// ---------------- launch --------------------------------------------------------
extern "C" void kernel_launch(void* const* d_in, const int* in_sizes, int n_in,
                              void* d_out, int out_size) {
    (void)in_sizes; (void)n_in; (void)out_size;
    cudaFuncSetAttribute(attn_decoder_fused,
                         cudaFuncAttributeMaxDynamicSharedMemorySize,
                         (int)sizeof(SmemLayout));
    attn_decoder_fused<<<NB, NT, sizeof(SmemLayout)>>>(
        (const int*)d_in[0],  (const float*)d_in[1], (const float*)d_in[2],
        (const int*)d_in[3],  (const int*)d_in[4],   (const float*)d_in[5],
        (const float*)d_in[6],(const float*)d_in[7], (const float*)d_in[8],
        (const float*)d_in[9],(const float*)d_in[10],(const float*)d_in[11],
        (const float*)d_in[12],(const float*)d_in[13],(const float*)d_in[14],
        (const float*)d_in[15],(const float*)d_in[16],(const float*)d_in[17],
        (float*)d_out);
}